// round 1
// baseline (speedup 1.0000x reference)
#include <cuda_runtime.h>
#include <cuda_bf16.h>
#include <cstdint>

// Problem constants (shapes fixed by the dataset):
//   L_F=32, HOP=16, DELTA=3, L_S=96, COND=32, GH=64, B=128, T=48000
//   Nf = (T-32)/16+1 = 2999, Ns = (T-96)/48+1 = 999
#define BSZ    128
#define T_MAX  48000
#define NS_MAX 999
#define NF_MAX 2999

// -------- scratch (device globals; no allocations allowed) --------
__device__ float g_gi[(size_t)BSZ * NS_MAX * 192];  // GRU input gates      (~98 MB)
__device__ float g_hs[(size_t)BSZ * NS_MAX * 64];   // GRU hidden states    (~33 MB)
__device__ float g_cs[(size_t)BSZ * NS_MAX * 32];   // conditioning vectors (~16 MB)
__device__ float g_y [(size_t)BSZ * NF_MAX * 32];   // per-frame outputs    (~49 MB)

// =====================================================================
// Kernel A: gi[b][s][j] = b_ih[j] + sum_k W_ih[j][k] * x[b, s*48+k]
// 64 threads, 3 rows/thread (j, j+64, j+128), 16 s-values per block.
// W_ih chunk staged in shared (padded stride 49 -> conflict-free).
// =====================================================================
#define A_STILE 16
__global__ void __launch_bounds__(64) gi_kernel(const float* __restrict__ x,
                                                const float* __restrict__ W_ih,
                                                const float* __restrict__ b_ih,
                                                int T, int Ns) {
    __shared__ float Wsh[192 * 49];                       // 36.75 KB
    __shared__ float xsh[96 + (A_STILE - 1) * 48];        // 816 floats

    const int b  = blockIdx.y;
    const int s0 = blockIdx.x * A_STILE;
    const int j  = threadIdx.x;                           // 0..63

    int nvalid = Ns - s0; if (nvalid > A_STILE) nvalid = A_STILE;
    const float* xb = x + (size_t)b * T;
    const int span = 96 + (nvalid - 1) * 48;
    for (int i = j; i < span; i += 64) xsh[i] = xb[s0 * 48 + i];

    float acc0[A_STILE], acc1[A_STILE], acc2[A_STILE];
    #pragma unroll
    for (int s = 0; s < A_STILE; s++) { acc0[s] = 0.f; acc1[s] = 0.f; acc2[s] = 0.f; }

    for (int kc = 0; kc < 2; kc++) {
        __syncthreads();
        // stage 192x48 chunk of W_ih
        for (int i = j; i < 192 * 48; i += 64) {
            int r = i / 48, c = i % 48;
            Wsh[r * 49 + c] = W_ih[r * 96 + kc * 48 + c];
        }
        __syncthreads();
        #pragma unroll 4
        for (int k = 0; k < 48; k++) {
            const float w0 = Wsh[(j       ) * 49 + k];
            const float w1 = Wsh[(j +  64 ) * 49 + k];
            const float w2 = Wsh[(j + 128 ) * 49 + k];
            const int xo = kc * 48 + k;
            #pragma unroll
            for (int s = 0; s < A_STILE; s++) {
                const float xv = xsh[s * 48 + xo];
                acc0[s] = fmaf(w0, xv, acc0[s]);
                acc1[s] = fmaf(w1, xv, acc1[s]);
                acc2[s] = fmaf(w2, xv, acc2[s]);
            }
        }
    }
    const float bb0 = b_ih[j], bb1 = b_ih[j + 64], bb2 = b_ih[j + 128];
    for (int s = 0; s < nvalid; s++) {
        const size_t base = ((size_t)b * Ns + (s0 + s)) * 192;
        g_gi[base + j      ] = acc0[s] + bb0;
        g_gi[base + j + 64 ] = acc1[s] + bb1;
        g_gi[base + j + 128] = acc2[s] + bb2;
    }
}

// =====================================================================
// Kernel B: GRU recurrence. 1 block per batch row, 192 threads.
// Thread j owns W_hh row j in registers; h lives in shared.
// =====================================================================
__global__ void __launch_bounds__(192, 1) gru_kernel(const float* __restrict__ W_hh,
                                                     const float* __restrict__ b_hh,
                                                     int Ns) {
    __shared__ __align__(16) float h_sh[64];
    __shared__ float gh_sh[192];
    __shared__ float gi_sh[192];

    const int b = blockIdx.x;
    const int j = threadIdx.x;

    float wrow[64];
    #pragma unroll
    for (int k = 0; k < 64; k += 4) {
        const float4 v = *reinterpret_cast<const float4*>(&W_hh[j * 64 + k]);
        wrow[k] = v.x; wrow[k + 1] = v.y; wrow[k + 2] = v.z; wrow[k + 3] = v.w;
    }
    const float bj = b_hh[j];
    if (j < 64) h_sh[j] = 0.f;
    __syncthreads();

    const float* gib = g_gi + (size_t)b * Ns * 192;
    float*       hsb = g_hs + (size_t)b * Ns * 64;

    for (int t = 0; t < Ns; t++) {
        const float gv = __ldg(&gib[t * 192 + j]);   // independent: issued early
        float acc = bj;
        #pragma unroll
        for (int k = 0; k < 64; k += 4) {
            const float4 hv = *reinterpret_cast<const float4*>(&h_sh[k]);
            acc = fmaf(wrow[k    ], hv.x, acc);
            acc = fmaf(wrow[k + 1], hv.y, acc);
            acc = fmaf(wrow[k + 2], hv.z, acc);
            acc = fmaf(wrow[k + 3], hv.w, acc);
        }
        gh_sh[j] = acc;
        gi_sh[j] = gv;
        __syncthreads();
        if (j < 64) {
            const float r  = 1.f / (1.f + __expf(-(gi_sh[j]       + gh_sh[j]      )));
            const float z  = 1.f / (1.f + __expf(-(gi_sh[j + 64]  + gh_sh[j + 64] )));
            const float n  = tanhf(gi_sh[j + 128] + r * gh_sh[j + 128]);
            const float h  = h_sh[j];
            const float hn = (1.f - z) * n + z * h;
            h_sh[j]   = hn;
            hsb[t * 64 + j] = hn;                    // fire-and-forget store
        }
        __syncthreads();
    }
}

// =====================================================================
// Kernel B2: c_s[b][t][i] = b_cs[i] + sum_k W_cs[i][k] * hs[b][t][k]
// 256 threads: 8 t-values x 32 outputs per block.
// =====================================================================
__global__ void __launch_bounds__(256) cs_kernel(const float* __restrict__ W_cs,
                                                 const float* __restrict__ b_cs,
                                                 int Ns) {
    __shared__ float wsh[64 * 32];   // [k][i] = W_cs[i][k]
    __shared__ float hsh[8 * 64];

    const int b  = blockIdx.y;
    const int t0 = blockIdx.x * 8;
    const int tid = threadIdx.x;

    for (int i = tid; i < 2048; i += 256) {
        const int k = i >> 5, ii = i & 31;
        wsh[i] = W_cs[ii * 64 + k];
    }
    const int nvalid = min(8, Ns - t0);
    for (int i = tid; i < nvalid * 64; i += 256)
        hsh[i] = g_hs[((size_t)b * Ns + t0) * 64 + i];
    __syncthreads();

    const int tl = tid >> 5, ii = tid & 31;
    if (tl < nvalid) {
        float acc = b_cs[ii];
        #pragma unroll
        for (int k = 0; k < 64; k++)
            acc = fmaf(wsh[k * 32 + ii], hsh[tl * 64 + k], acc);
        g_cs[((size_t)b * Ns + (t0 + tl)) * 32 + ii] = acc;
    }
}

// =====================================================================
// Kernel C: fast path. 64 threads, 32 frames per block.
//   feat = [x[b, n*16 .. n*16+31], c_s[b, clip(n/3-1,0)]]
//   h = relu(W1 @ feat + b1);  y = W2 @ h + b2
// W1 row j and W2 row j (j<32) register-resident.
// =====================================================================
#define C_FT 32
__global__ void __launch_bounds__(64) fast_kernel(const float* __restrict__ x,
                                                  const float* __restrict__ W1,
                                                  const float* __restrict__ b1,
                                                  const float* __restrict__ W2,
                                                  const float* __restrict__ b2,
                                                  int T, int Nf, int Ns) {
    __shared__ float xsh[32 + (C_FT - 1) * 16];   // 528 floats
    __shared__ float csh[C_FT * 32];
    __shared__ float hsh[64];

    const int b  = blockIdx.y;
    const int n0 = blockIdx.x * C_FT;
    const int j  = threadIdx.x;

    const int nv = min(C_FT, Nf - n0);
    const float* xb = x + (size_t)b * T;
    const int span = 32 + (nv - 1) * 16;
    for (int i = j; i < span; i += 64) xsh[i] = xb[n0 * 16 + i];
    for (int i = j; i < nv * 32; i += 64) {
        const int f = i >> 5, k = i & 31;
        int cn = (n0 + f) / 3 - 1; if (cn < 0) cn = 0;
        csh[i] = g_cs[((size_t)b * Ns + cn) * 32 + k];
    }

    float w1r[64];
    #pragma unroll
    for (int k = 0; k < 64; k++) w1r[k] = W1[j * 64 + k];
    float w2r[64];
    if (j < 32) {
        #pragma unroll
        for (int k = 0; k < 64; k++) w2r[k] = W2[j * 64 + k];
    }
    const float b1j = b1[j];
    const float b2j = (j < 32) ? b2[j] : 0.f;
    __syncthreads();

    for (int f = 0; f < nv; f++) {
        float acc = b1j;
        #pragma unroll
        for (int k = 0; k < 32; k++) acc = fmaf(w1r[k],      xsh[f * 16 + k], acc);
        #pragma unroll
        for (int k = 0; k < 32; k++) acc = fmaf(w1r[32 + k], csh[f * 32 + k], acc);
        hsh[j] = fmaxf(acc, 0.f);
        __syncthreads();
        if (j < 32) {
            float y = b2j;
            #pragma unroll
            for (int k = 0; k < 64; k++) y = fmaf(w2r[k], hsh[k], y);
            g_y[((size_t)b * Nf + (n0 + f)) * 32 + j] = y;
        }
        __syncthreads();
    }
}

// =====================================================================
// Kernel D: overlap-add as a gather. Each sample t is covered by at
// most two frames: n0=t/16 (offset t%16) and n0-1 (offset t%16+16).
// =====================================================================
__global__ void __launch_bounds__(256) gather_kernel(float* __restrict__ out,
                                                     int T, int Nf) {
    const int idx = blockIdx.x * blockDim.x + threadIdx.x;
    const int total = BSZ * T;
    if (idx >= total) return;
    const int b = idx / T, t = idx % T;
    const int n0 = t >> 4, r = t & 15;
    const float* yb = g_y + (size_t)b * Nf * 32;
    float v = 0.f;
    if (n0 < Nf)            v += yb[n0 * 32 + r];
    if (n0 >= 1 && n0 - 1 < Nf) v += yb[(n0 - 1) * 32 + 16 + r];
    out[idx] = v;
}

// =====================================================================
extern "C" void kernel_launch(void* const* d_in, const int* in_sizes, int n_in,
                              void* d_out, int out_size) {
    const float* x    = (const float*)d_in[0];
    const float* W_ih = (const float*)d_in[1];
    const float* W_hh = (const float*)d_in[2];
    const float* b_ih = (const float*)d_in[3];
    const float* b_hh = (const float*)d_in[4];
    const float* W_cs = (const float*)d_in[5];
    const float* b_cs = (const float*)d_in[6];
    const float* W1   = (const float*)d_in[7];
    const float* b1   = (const float*)d_in[8];
    const float* W2   = (const float*)d_in[9];
    const float* b2   = (const float*)d_in[10];
    float* out = (float*)d_out;

    const int T  = in_sizes[0] / BSZ;
    const int Nf = (T - 32) / 16 + 1;
    const int Ns = (T - 96) / 48 + 1;

    gi_kernel   <<<dim3((Ns + A_STILE - 1) / A_STILE, BSZ), 64>>>(x, W_ih, b_ih, T, Ns);
    gru_kernel  <<<BSZ, 192>>>(W_hh, b_hh, Ns);
    cs_kernel   <<<dim3((Ns + 7) / 8, BSZ), 256>>>(W_cs, b_cs, Ns);
    fast_kernel <<<dim3((Nf + C_FT - 1) / C_FT, BSZ), 64>>>(x, W1, b1, W2, b2, T, Nf, Ns);
    gather_kernel<<<(BSZ * T + 255) / 256, 256>>>(out, T, Nf);
}

// round 2
// speedup vs baseline: 1.7119x; 1.7119x over previous
#include <cuda_runtime.h>
#include <cuda_bf16.h>
#include <cstdint>

// Shapes fixed by dataset: L_F=32, HOP=16, DELTA=3, L_S=96, COND=32, GH=64, B=128, T=48000
// Nf = 2999, Ns = 999
#define BSZ    128
#define NS_MAX 999
#define NF_MAX 2999

typedef unsigned long long u64t;

// ---------------- packed f32x2 helpers (sm_103a FFMA2 path) ----------------
__device__ __forceinline__ u64t ffma2(u64t a, u64t b, u64t c) {
    u64t d; asm("fma.rn.f32x2 %0, %1, %2, %3;" : "=l"(d) : "l"(a), "l"(b), "l"(c)); return d;
}
__device__ __forceinline__ u64t fadd2(u64t a, u64t b) {
    u64t d; asm("add.rn.f32x2 %0, %1, %2;" : "=l"(d) : "l"(a), "l"(b)); return d;
}
__device__ __forceinline__ u64t fpack2(float lo, float hi) {
    u64t d; asm("mov.b64 %0, {%1, %2};" : "=l"(d) : "f"(lo), "f"(hi)); return d;
}
__device__ __forceinline__ float2 funpack2(u64t v) {
    float2 f; asm("mov.b64 {%0, %1}, %2;" : "=f"(f.x), "=f"(f.y) : "l"(v)); return f;
}
__device__ __forceinline__ float hsum2(u64t v) { float2 f = funpack2(v); return f.x + f.y; }

// ---------------- scratch (device globals; no allocations allowed) ----------
__device__ float g_gi[(size_t)BSZ * NS_MAX * 192];
__device__ float g_hs[(size_t)BSZ * NS_MAX * 64];
__device__ float g_cs[(size_t)BSZ * NS_MAX * 32];
__device__ float g_y [(size_t)BSZ * NF_MAX * 32];

// =====================================================================
// Kernel A: gi[b][s][j] = b_ih[j] + W_ih[j,:] . x[b, s*48 : s*48+96]
// Thread-per-s; 96-float feature vector in registers (as 48 f32x2 pairs),
// W chunk (32 rows) in shared read as broadcast LDS.128, outputs staged
// through a padded shared transpose tile for fully coalesced stores.
// =====================================================================
__global__ void __launch_bounds__(128) gi_kernel(const float* __restrict__ x,
                                                 const float* __restrict__ W_ih,
                                                 const float* __restrict__ b_ih,
                                                 int T, int Ns) {
    __shared__ __align__(16) float Wc[32 * 96];     // 12.3 KB: 32-row chunk of W_ih
    __shared__ float tile[32 * 129];                // 16.5 KB transpose staging (pad 129)
    __shared__ float bsh[192];

    const int b   = blockIdx.y;
    const int s0  = blockIdx.x * 128;
    const int tid = threadIdx.x;
    const int s   = s0 + tid;
    const bool valid = (s < Ns);

    for (int i = tid; i < 192; i += 128) bsh[i] = b_ih[i];

    // feature vector -> registers as packed pairs
    u64t f2[48];
    if (valid) {
        const ulonglong2* xp = reinterpret_cast<const ulonglong2*>(x + (size_t)b * T + (size_t)s * 48);
        #pragma unroll
        for (int q = 0; q < 24; q++) { ulonglong2 v = xp[q]; f2[2*q] = v.x; f2[2*q+1] = v.y; }
    } else {
        #pragma unroll
        for (int i = 0; i < 48; i++) f2[i] = 0ULL;
    }

    int nv = Ns - s0; if (nv > 128) nv = 128;

    for (int jc = 0; jc < 6; jc++) {
        __syncthreads();                       // tile reads of prev chunk done
        const float* wsrc = W_ih + jc * 32 * 96;
        for (int i = tid; i < 32 * 96; i += 128) Wc[i] = wsrc[i];
        __syncthreads();

        #pragma unroll 1
        for (int jj = 0; jj < 32; jj++) {
            const ulonglong2* wv = reinterpret_cast<const ulonglong2*>(&Wc[jj * 96]);
            u64t a0 = 0ULL, a1 = 0ULL, a2 = 0ULL, a3 = 0ULL;
            #pragma unroll
            for (int p = 0; p < 24; p++) {     // LDS.128 broadcast, 2 FFMA2 each
                ulonglong2 w = wv[p];
                if (p & 1) { a2 = ffma2(w.x, f2[2*p], a2); a3 = ffma2(w.y, f2[2*p+1], a3); }
                else       { a0 = ffma2(w.x, f2[2*p], a0); a1 = ffma2(w.y, f2[2*p+1], a1); }
            }
            tile[jj * 129 + tid] = hsum2(fadd2(fadd2(a0, a1), fadd2(a2, a3))) + bsh[jc * 32 + jj];
        }
        __syncthreads();

        // coalesced store: each thread writes 8 float4 (lane -> consecutive j)
        #pragma unroll
        for (int it = 0; it < 8; it++) {
            int q  = tid + it * 128;           // float4 index in [0,1024)
            int j0 = (q & 7) * 4;
            int sl = q >> 3;
            if (sl < nv) {
                float4 v;
                v.x = tile[(j0    ) * 129 + sl];
                v.y = tile[(j0 + 1) * 129 + sl];
                v.z = tile[(j0 + 2) * 129 + sl];
                v.w = tile[(j0 + 3) * 129 + sl];
                *reinterpret_cast<float4*>(&g_gi[((size_t)b * Ns + s0 + sl) * 192 + jc * 32 + j0]) = v;
            }
        }
    }
}

// =====================================================================
// Kernel B: GRU recurrence. 1 block / batch row, 192 threads.
// Row j of W_hh register-resident as f32x2 pairs; 4-way split accumulators
// (short dep chain); next-step gi prefetched across the whole step body.
// =====================================================================
__global__ void __launch_bounds__(192, 1) gru_kernel(const float* __restrict__ W_hh,
                                                     const float* __restrict__ b_hh,
                                                     int Ns) {
    __shared__ __align__(16) float h_sh[64];
    __shared__ float gh_sh[192];
    __shared__ float gi_sh[192];

    const int b = blockIdx.x;
    const int j = threadIdx.x;

    u64t wr[32];
    {
        const ulonglong2* wsrc = reinterpret_cast<const ulonglong2*>(W_hh + j * 64);
        #pragma unroll
        for (int p = 0; p < 16; p++) { ulonglong2 v = wsrc[p]; wr[2*p] = v.x; wr[2*p+1] = v.y; }
    }
    const float bj = b_hh[j];
    if (j < 64) h_sh[j] = 0.f;
    __syncthreads();

    const float* gib = g_gi + (size_t)b * Ns * 192;
    float*       hsb = g_hs + (size_t)b * Ns * 64;

    float gv = __ldg(&gib[j]);
    for (int t = 0; t < Ns; t++) {
        float gv_next = (t + 1 < Ns) ? __ldg(&gib[(t + 1) * 192 + j]) : 0.f;

        const ulonglong2* hv = reinterpret_cast<const ulonglong2*>(h_sh);
        u64t a0 = 0ULL, a1 = 0ULL, a2 = 0ULL, a3 = 0ULL;
        #pragma unroll
        for (int p = 0; p < 16; p++) {
            ulonglong2 h4 = hv[p];
            if (p & 1) { a2 = ffma2(wr[2*p], h4.x, a2); a3 = ffma2(wr[2*p+1], h4.y, a3); }
            else       { a0 = ffma2(wr[2*p], h4.x, a0); a1 = ffma2(wr[2*p+1], h4.y, a1); }
        }
        gh_sh[j] = hsum2(fadd2(fadd2(a0, a1), fadd2(a2, a3))) + bj;
        gi_sh[j] = gv;
        __syncthreads();

        if (j < 64) {
            const float r  = 1.f / (1.f + __expf(-(gi_sh[j]       + gh_sh[j]      )));
            const float z  = 1.f / (1.f + __expf(-(gi_sh[j + 64]  + gh_sh[j + 64] )));
            const float n  = tanhf(gi_sh[j + 128] + r * gh_sh[j + 128]);
            const float hn = (1.f - z) * n + z * h_sh[j];
            h_sh[j] = hn;
            hsb[t * 64 + j] = hn;
        }
        __syncthreads();
        gv = gv_next;
    }
}

// =====================================================================
// Kernel B2: c_s = hs @ W_cs.T + b_cs   (small; unchanged structure)
// =====================================================================
__global__ void __launch_bounds__(256) cs_kernel(const float* __restrict__ W_cs,
                                                 const float* __restrict__ b_cs,
                                                 int Ns) {
    __shared__ float wsh[64 * 32];   // [k][i]
    __shared__ float hsh[8 * 64];

    const int b  = blockIdx.y;
    const int t0 = blockIdx.x * 8;
    const int tid = threadIdx.x;

    for (int i = tid; i < 2048; i += 256) {
        const int k = i >> 5, ii = i & 31;
        wsh[i] = W_cs[ii * 64 + k];
    }
    const int nvalid = min(8, Ns - t0);
    for (int i = tid; i < nvalid * 64; i += 256)
        hsh[i] = g_hs[((size_t)b * Ns + t0) * 64 + i];
    __syncthreads();

    const int tl = tid >> 5, ii = tid & 31;
    if (tl < nvalid) {
        float acc = b_cs[ii];
        #pragma unroll
        for (int k = 0; k < 64; k++)
            acc = fmaf(wsh[k * 32 + ii], hsh[tl * 64 + k], acc);
        g_cs[((size_t)b * Ns + (t0 + tl)) * 32 + ii] = acc;
    }
}

// =====================================================================
// Kernel C: fast path, thread-per-frame.
//   feat(64) in registers, W1 in shared (LDS.128 broadcast),
//   stage2 fused: y += W2T[:,j]*h_j as h_j is produced (no h array).
// =====================================================================
__global__ void __launch_bounds__(128) fast_kernel(const float* __restrict__ x,
                                                   const float* __restrict__ W1,
                                                   const float* __restrict__ b1,
                                                   const float* __restrict__ W2,
                                                   const float* __restrict__ b2,
                                                   int T, int Nf, int Ns) {
    __shared__ __align__(16) float W1sh[64 * 64];   // [j][k]
    __shared__ __align__(16) float W2T[64 * 32];    // [j][i]
    __shared__ float b1sh[64];
    __shared__ u64t  b2sh[16];

    const int b   = blockIdx.y;
    const int tid = threadIdx.x;
    const int n   = blockIdx.x * 128 + tid;

    for (int i = tid; i < 4096; i += 128) W1sh[i] = W1[i];
    for (int i = tid; i < 2048; i += 128) { int jj = i >> 5, ii = i & 31; W2T[i] = W2[ii * 64 + jj]; }
    if (tid < 64) b1sh[tid] = b1[tid];
    if (tid < 16) b2sh[tid] = fpack2(b2[2 * tid], b2[2 * tid + 1]);
    __syncthreads();

    if (n >= Nf) return;

    u64t xf[16], cf[16];
    {
        const ulonglong2* xp = reinterpret_cast<const ulonglong2*>(x + (size_t)b * T + (size_t)n * 16);
        #pragma unroll
        for (int q = 0; q < 8; q++) { ulonglong2 v = xp[q]; xf[2*q] = v.x; xf[2*q+1] = v.y; }
        int cn = n / 3 - 1; if (cn < 0) cn = 0;
        const ulonglong2* cp = reinterpret_cast<const ulonglong2*>(g_cs + ((size_t)b * Ns + cn) * 32);
        #pragma unroll
        for (int q = 0; q < 8; q++) { ulonglong2 v = cp[q]; cf[2*q] = v.x; cf[2*q+1] = v.y; }
    }

    u64t y2[16];
    #pragma unroll
    for (int i = 0; i < 16; i++) y2[i] = 0ULL;

    #pragma unroll 1
    for (int jj = 0; jj < 64; jj++) {
        const ulonglong2* w1v = reinterpret_cast<const ulonglong2*>(&W1sh[jj * 64]);
        u64t a0 = 0ULL, a1 = 0ULL, a2 = 0ULL, a3 = 0ULL;
        #pragma unroll
        for (int p = 0; p < 8; p++) {          // x half
            ulonglong2 w = w1v[p];
            a0 = ffma2(w.x, xf[2*p], a0); a1 = ffma2(w.y, xf[2*p+1], a1);
        }
        #pragma unroll
        for (int p = 0; p < 8; p++) {          // c half
            ulonglong2 w = w1v[8 + p];
            a2 = ffma2(w.x, cf[2*p], a2); a3 = ffma2(w.y, cf[2*p+1], a3);
        }
        float h = hsum2(fadd2(fadd2(a0, a1), fadd2(a2, a3))) + b1sh[jj];
        h = fmaxf(h, 0.f);
        u64t h2 = fpack2(h, h);
        const ulonglong2* w2v = reinterpret_cast<const ulonglong2*>(&W2T[jj * 32]);
        #pragma unroll
        for (int p = 0; p < 8; p++) {          // fused stage-2 rank-1 update
            ulonglong2 w = w2v[p];
            y2[2*p] = ffma2(w.x, h2, y2[2*p]); y2[2*p+1] = ffma2(w.y, h2, y2[2*p+1]);
        }
    }

    float4* yo = reinterpret_cast<float4*>(&g_y[((size_t)b * Nf + n) * 32]);
    #pragma unroll
    for (int p = 0; p < 8; p++) {
        float2 va = funpack2(fadd2(y2[2*p],     b2sh[2*p]));
        float2 vb = funpack2(fadd2(y2[2*p + 1], b2sh[2*p + 1]));
        yo[p] = make_float4(va.x, va.y, vb.x, vb.y);
    }
}

// =====================================================================
// Kernel D: overlap-add as gather (each sample covered by <=2 frames).
// =====================================================================
__global__ void __launch_bounds__(256) gather_kernel(float* __restrict__ out,
                                                     int T, int Nf) {
    const int idx = blockIdx.x * blockDim.x + threadIdx.x;
    const int total = BSZ * T;
    if (idx >= total) return;
    const int b = idx / T, t = idx % T;
    const int n0 = t >> 4, r = t & 15;
    const float* yb = g_y + (size_t)b * Nf * 32;
    float v = 0.f;
    if (n0 < Nf)                 v += yb[n0 * 32 + r];
    if (n0 >= 1 && n0 - 1 < Nf)  v += yb[(n0 - 1) * 32 + 16 + r];
    out[idx] = v;
}

// =====================================================================
extern "C" void kernel_launch(void* const* d_in, const int* in_sizes, int n_in,
                              void* d_out, int out_size) {
    const float* x    = (const float*)d_in[0];
    const float* W_ih = (const float*)d_in[1];
    const float* W_hh = (const float*)d_in[2];
    const float* b_ih = (const float*)d_in[3];
    const float* b_hh = (const float*)d_in[4];
    const float* W_cs = (const float*)d_in[5];
    const float* b_cs = (const float*)d_in[6];
    const float* W1   = (const float*)d_in[7];
    const float* b1   = (const float*)d_in[8];
    const float* W2   = (const float*)d_in[9];
    const float* b2   = (const float*)d_in[10];
    float* out = (float*)d_out;

    const int T  = in_sizes[0] / BSZ;
    const int Nf = (T - 32) / 16 + 1;
    const int Ns = (T - 96) / 48 + 1;

    gi_kernel    <<<dim3((Ns + 127) / 128, BSZ), 128>>>(x, W_ih, b_ih, T, Ns);
    gru_kernel   <<<BSZ, 192>>>(W_hh, b_hh, Ns);
    cs_kernel    <<<dim3((Ns + 7) / 8, BSZ), 256>>>(W_cs, b_cs, Ns);
    fast_kernel  <<<dim3((Nf + 127) / 128, BSZ), 128>>>(x, W1, b1, W2, b2, T, Nf, Ns);
    gather_kernel<<<(BSZ * T + 255) / 256, 256>>>(out, T, Nf);
}